// round 8
// baseline (speedup 1.0000x reference)
#include <cuda_runtime.h>
#include <cuda_fp16.h>

#define Bb   8
#define Nn   2048
#define FIN  128
#define FOUT 64
#define NSTRIP 4
#define JS   (Nn / NSTRIP)          // 512 j per strip
#define ROWS (Bb * Nn)              // 16384
#define K1BLK 512                   // k1 blocks inside fused kernel
#define PACKBLK (ROWS / 4)          // 4096 pack blocks (4 warps x 1 row)

typedef unsigned int u32;

// ---------------- device scratch (no allocations allowed) ----------------
__device__ float g_E1[ROWS], g_E2[ROWS], g_F1[ROWS], g_F2[ROWS];
__device__ __half g_hHi[ROWS * FOUT];
__device__ u32   g_mask[ROWS * 64];              // 4.2 MB adjacency bitmask
__device__ float g_part[NSTRIP * ROWS * FOUT];   // 16.8 MB partial numerators
__device__ float g_den [NSTRIP * ROWS];          // partial denominators

// ---------------- MMA helpers (sm_80 baseline PTX) ----------------
__device__ __forceinline__ void ldsm4(u32& r0, u32& r1, u32& r2, u32& r3, u32 a) {
    asm volatile("ldmatrix.sync.aligned.m8n8.x4.shared.b16 {%0,%1,%2,%3}, [%4];"
                 : "=r"(r0), "=r"(r1), "=r"(r2), "=r"(r3) : "r"(a));
}
__device__ __forceinline__ void ldsm4t(u32& r0, u32& r1, u32& r2, u32& r3, u32 a) {
    asm volatile("ldmatrix.sync.aligned.m8n8.x4.trans.shared.b16 {%0,%1,%2,%3}, [%4];"
                 : "=r"(r0), "=r"(r1), "=r"(r2), "=r"(r3) : "r"(a));
}
__device__ __forceinline__ void ldsm2t(u32& r0, u32& r1, u32 a) {
    asm volatile("ldmatrix.sync.aligned.m8n8.x2.trans.shared.b16 {%0,%1}, [%2];"
                 : "=r"(r0), "=r"(r1) : "r"(a));
}
__device__ __forceinline__ void hmma(float* c, const u32* a, u32 b0, u32 b1) {
    asm volatile("mma.sync.aligned.m16n8k16.row.col.f32.f16.f16.f32 "
                 "{%0,%1,%2,%3}, {%4,%5,%6,%7}, {%8,%9}, {%0,%1,%2,%3};"
                 : "+f"(c[0]), "+f"(c[1]), "+f"(c[2]), "+f"(c[3])
                 : "r"(a[0]), "r"(a[1]), "r"(a[2]), "r"(a[3]), "r"(b0), "r"(b1));
}
__device__ __forceinline__ u32 smem_u32(const void* p) {
    u32 a;
    asm("{ .reg .u64 t; cvta.to.shared.u64 t, %1; cvt.u32.u64 %0, t; }" : "=r"(a) : "l"(p));
    return a;
}

// ---------------- K1 fused: proj (blocks < K1BLK) + adj bit-pack ----------
// Pack layout: per row, word w = g*4+s (g = j>>7, s = j&3) has bit l = adj bit
// for j = g*128 + l*4 + s. k2 consumes one uint4 (words g*4..g*4+3) per row.
__global__ __launch_bounds__(128) void k1_fused(const float* __restrict__ x,
                                                const float* __restrict__ W,
                                                const float* __restrict__ a,
                                                const int* __restrict__ adj) {
    __shared__ float sX[32][132];
    __shared__ float sW[FIN][FOUT];
    __shared__ float sa[2 * FOUT];
    __shared__ float sp1[32][17], sp2[32][17];

    int t = threadIdx.x;
    if (blockIdx.x >= K1BLK) {
        // ---- adjacency bit-pack: warp per row, int4 loads + 4 ballots each --
        int lane = t & 31;
        int row = (blockIdx.x - K1BLK) * 4 + (t >> 5);
        const int4* rowp = (const int4*)(adj + (size_t)row * Nn);
        u32* mrow = g_mask + (size_t)row * 64;
#pragma unroll
        for (int c = 0; c < 2; c++) {
            int4 v[8];
#pragma unroll
            for (int q = 0; q < 8; q++) v[q] = rowp[c * 256 + q * 32 + lane];
            u32 myword = 0;
#pragma unroll
            for (int q = 0; q < 8; q++) {
                u32 b0 = __ballot_sync(0xffffffffu, v[q].x > 0);
                u32 b1 = __ballot_sync(0xffffffffu, v[q].y > 0);
                u32 b2 = __ballot_sync(0xffffffffu, v[q].z > 0);
                u32 b3 = __ballot_sync(0xffffffffu, v[q].w > 0);
                myword = (lane == q * 4 + 0) ? b0 : myword;
                myword = (lane == q * 4 + 1) ? b1 : myword;
                myword = (lane == q * 4 + 2) ? b2 : myword;
                myword = (lane == q * 4 + 3) ? b3 : myword;
            }
            mrow[c * 32 + lane] = myword;
        }
        return;
    }

    // ---- projection: h = x@W (f16), per-node exps ----
    int r0 = blockIdx.x * 32;
#pragma unroll
    for (int q = 0; q < 16; q++)
        ((float4*)sW)[t + q * 128] = ((const float4*)W)[t + q * 128];
    sa[t] = a[t];
#pragma unroll
    for (int q = 0; q < 8; q++) {
        int idx = t + q * 128;
        int row = idx >> 5, c4 = idx & 31;
        *(float4*)&sX[row][c4 * 4] = ((const float4*)(x + (size_t)(r0 + row) * FIN))[c4];
    }
    __syncthreads();

    int rowt = t >> 4, colt = t & 15;
    float acc[4][4] = {};
#pragma unroll 4
    for (int k = 0; k < FIN; k++) {
        float4 wv = *(const float4*)&sW[k][colt * 4];
        float x0 = sX[rowt * 4 + 0][k], x1 = sX[rowt * 4 + 1][k];
        float x2 = sX[rowt * 4 + 2][k], x3 = sX[rowt * 4 + 3][k];
        acc[0][0] = fmaf(x0, wv.x, acc[0][0]); acc[0][1] = fmaf(x0, wv.y, acc[0][1]);
        acc[0][2] = fmaf(x0, wv.z, acc[0][2]); acc[0][3] = fmaf(x0, wv.w, acc[0][3]);
        acc[1][0] = fmaf(x1, wv.x, acc[1][0]); acc[1][1] = fmaf(x1, wv.y, acc[1][1]);
        acc[1][2] = fmaf(x1, wv.z, acc[1][2]); acc[1][3] = fmaf(x1, wv.w, acc[1][3]);
        acc[2][0] = fmaf(x2, wv.x, acc[2][0]); acc[2][1] = fmaf(x2, wv.y, acc[2][1]);
        acc[2][2] = fmaf(x2, wv.z, acc[2][2]); acc[2][3] = fmaf(x2, wv.w, acc[2][3]);
        acc[3][0] = fmaf(x3, wv.x, acc[3][0]); acc[3][1] = fmaf(x3, wv.y, acc[3][1]);
        acc[3][2] = fmaf(x3, wv.z, acc[3][2]); acc[3][3] = fmaf(x3, wv.w, acc[3][3]);
    }

    float a1v[4] = {sa[colt * 4], sa[colt * 4 + 1], sa[colt * 4 + 2], sa[colt * 4 + 3]};
    float a2v[4] = {sa[64 + colt * 4], sa[64 + colt * 4 + 1],
                    sa[64 + colt * 4 + 2], sa[64 + colt * 4 + 3]};
#pragma unroll
    for (int r = 0; r < 4; r++) {
        int row = rowt * 4 + r;
        float p1 = acc[r][0] * a1v[0] + acc[r][1] * a1v[1]
                 + acc[r][2] * a1v[2] + acc[r][3] * a1v[3];
        float p2 = acc[r][0] * a2v[0] + acc[r][1] * a2v[1]
                 + acc[r][2] * a2v[2] + acc[r][3] * a2v[3];
        sp1[row][colt] = p1;
        sp2[row][colt] = p2;
        __half2 h0 = __floats2half2_rn(acc[r][0], acc[r][1]);
        __half2 h1 = __floats2half2_rn(acc[r][2], acc[r][3]);
        size_t o = (size_t)(r0 + row) * FOUT + colt * 4;
        *(uint2*)&g_hHi[o] = make_uint2(*(u32*)&h0, *(u32*)&h1);
    }
    __syncthreads();
    if (t < 32) {
        float s1 = 0.f, s2 = 0.f;
#pragma unroll
        for (int q = 0; q < 16; q++) { s1 += sp1[t][q]; s2 += sp2[t][q]; }
        int gr = r0 + t;
        g_E1[gr] = __expf(s1);  g_E2[gr] = __expf(0.2f * s1);
        g_F1[gr] = __expf(s2);  g_F2[gr] = __expf(0.2f * s2);
    }
}

// ---------------- K2: masked-softmax attention numerator via HMMA ----------
// grid (32 i-tiles, 8 b, 4 strips), 128 threads. adj via bitmask (broadcast
// LDG.128 per row-chunk). Denominator via ones-column at h-tile col 64.
#define PSTRB 144   // bytes per smem tile row (72 f16: 64 data + 8 pad/ones)
__global__ __launch_bounds__(128, 8) void k2_attn() {
    __shared__ __align__(16) __half sPh [64 * 72];
    __shared__ __align__(16) __half sHhi[64 * 72];
    __shared__ float2 sF[64];
    __shared__ float  sE1[64], sE2[64];

    const int t = threadIdx.x, lane = t & 31, w = t >> 5;
    const int b = blockIdx.y, i0 = blockIdx.x * 64, strip = blockIdx.z;
    const int jbase = strip * JS;

    if (t < 64) { sE1[t] = g_E1[b * Nn + i0 + t]; sE2[t] = g_E2[b * Nn + i0 + t]; }
    // ones-column init (cols 64-71 pad region; phase1 never touches it)
    if (t < 64)
        *(uint4*)((char*)sHhi + t * PSTRB + 128) = make_uint4(0x00003C00u, 0, 0, 0);

    const int rg = t >> 4, jsw = t & 15, js = jsw * 4;
    const u32* mbase = g_mask + (size_t)(b * Nn + i0) * 64;

    float acc[8][4];
#pragma unroll
    for (int n = 0; n < 8; n++)
#pragma unroll
        for (int q = 0; q < 4; q++) acc[n][q] = 0.f;
    float accD[4] = {0.f, 0.f, 0.f, 0.f};

    const u32 pHB = smem_u32(sPh);
    const u32 hHiB = smem_u32(sHhi);
    const u32 aOff = (u32)(w * 16 + (lane & 15)) * PSTRB + (u32)((lane >> 4) & 1) * 16;
    const u32 hRow = (u32)((lane & 7) + ((lane >> 4) & 1) * 8);
    const u32 hCol = (u32)((lane >> 3) & 1) * 16;
    const u32 oAddr0 = (u32)(lane & 15) * PSTRB;

    for (int c = 0; c < JS / 64; c++) {
        const int j0 = jbase + c * 64;
        const int g4 = (j0 >> 7) * 4;                 // uint4 word base for this chunk
        const u32 l  = (u32)(((j0 >> 2) + jsw) & 31); // bit index within words
        __syncthreads();                              // previous MMA done
        // ---- phase 1: load h tile + F + mask words ----
        if (t < 64) sF[t] = make_float2(g_F1[b * Nn + j0 + t], g_F2[b * Nn + j0 + t]);
        uint4 m4[8];
#pragma unroll
        for (int p = 0; p < 8; p++)
            m4[p] = *(const uint4*)(mbase + (size_t)(p * 8 + rg) * 64 + g4);
#pragma unroll
        for (int q = 0; q < 4; q++) {
            int u = t + q * 128;
            int row = u >> 3, c16 = u & 7;
            uint4 v = *(const uint4*)(g_hHi + ((size_t)(b * Nn) + j0 + row) * FOUT + c16 * 8);
            *(uint4*)((char*)sHhi + row * PSTRB + c16 * 16) = v;
        }
        __syncthreads();
        // ---- phase 2: P-gen (single f16 round) ----
        float2 f0 = sF[js], f1 = sF[js + 1], f2 = sF[js + 2], f3 = sF[js + 3];
#pragma unroll
        for (int p = 0; p < 8; p++) {
            int il = p * 8 + rg;
            float e1 = sE1[il], e2 = sE2[il];
            float w0 = ((m4[p].x >> l) & 1u) ? fmaxf(e1 * f0.x, e2 * f0.y) : 0.f;
            float w1 = ((m4[p].y >> l) & 1u) ? fmaxf(e1 * f1.x, e2 * f1.y) : 0.f;
            float w2 = ((m4[p].z >> l) & 1u) ? fmaxf(e1 * f2.x, e2 * f2.y) : 0.f;
            float w3 = ((m4[p].w >> l) & 1u) ? fmaxf(e1 * f3.x, e2 * f3.y) : 0.f;
            __half2 q0 = __floats2half2_rn(w0, w1);
            __half2 q1 = __floats2half2_rn(w2, w3);
            *(uint2*)((char*)sPh + il * PSTRB + js * 2) = make_uint2(*(u32*)&q0, *(u32*)&q1);
        }
        __syncthreads();
        // ---- phase 3: MMA (P*Hhi + P*ones) ----
#pragma unroll
        for (int ks = 0; ks < 4; ks++) {
            u32 af[4];
            ldsm4(af[0], af[1], af[2], af[3], pHB + aOff + ks * 32);
            u32 ho = (u32)(ks * 16 + hRow) * PSTRB + hCol;
#pragma unroll
            for (int np = 0; np < 4; np++) {
                u32 b0, b1, b2, b3;
                ldsm4t(b0, b1, b2, b3, hHiB + ho + np * 32);
                hmma(acc[np * 2],     af, b0, b2);
                hmma(acc[np * 2 + 1], af, b1, b3);
            }
            u32 d0, d1;
            ldsm2t(d0, d1, hHiB + (u32)(ks * 16) * PSTRB + oAddr0 + 128);
            hmma(accD, af, d0, d1);
        }
    }

    // ---- denominator (ones column): lanes with lane%4==0 hold col 64 ----
    if ((lane & 3) == 0) {
        size_t dbase = (size_t)strip * ROWS + b * Nn + i0 + w * 16 + (lane >> 2);
        g_den[dbase]     = accD[0];
        g_den[dbase + 8] = accD[2];
    }

    // ---- numerator partials: D fragments -> g_part ----
    float* base = g_part + (((size_t)strip * ROWS) + b * Nn + i0 + w * 16 + (lane >> 2))
                           * FOUT + (lane & 3) * 2;
#pragma unroll
    for (int nt = 0; nt < 8; nt++) {
        *(float2*)(base + nt * 8)            = make_float2(acc[nt][0], acc[nt][1]);
        *(float2*)(base + 8 * FOUT + nt * 8) = make_float2(acc[nt][2], acc[nt][3]);
    }
}

// ---------------- K3: combine strips, softmax-normalize, LN + ELU ----------
__global__ __launch_bounds__(256) void k3_fin(const float* __restrict__ gamma,
                                              const float* __restrict__ beta,
                                              float* __restrict__ out) {
    int warp = threadIdx.x >> 5, lane = threadIdx.x & 31;
    size_t row = (size_t)blockIdx.x * 8 + warp;
    int f0 = lane * 2;
    float2 v = make_float2(0.f, 0.f);
    float den = 0.f;
#pragma unroll
    for (int s = 0; s < NSTRIP; s++) {
        float2 pv = *(const float2*)(g_part + ((size_t)s * ROWS + row) * FOUT + f0);
        v.x += pv.x; v.y += pv.y;
        den += g_den[(size_t)s * ROWS + row];
    }
    float rinv = __fdividef(1.0f, den);
    v.x *= rinv; v.y *= rinv;
    float sum = v.x + v.y;
#pragma unroll
    for (int o = 16; o; o >>= 1) sum += __shfl_xor_sync(0xffffffffu, sum, o);
    float mu = sum * (1.0f / 64.0f);
    float dx = v.x - mu, dy = v.y - mu;
    float q = dx * dx + dy * dy;
#pragma unroll
    for (int o = 16; o; o >>= 1) q += __shfl_xor_sync(0xffffffffu, q, o);
    float rstd = rsqrtf(q * (1.0f / 64.0f) + 1e-5f);
    float y0 = dx * rstd * gamma[f0]     + beta[f0];
    float y1 = dy * rstd * gamma[f0 + 1] + beta[f0 + 1];
    float2 o2;
    o2.x = (y0 > 0.f) ? y0 : (__expf(y0) - 1.0f);
    o2.y = (y1 > 0.f) ? y1 : (__expf(y1) - 1.0f);
    *(float2*)(out + row * FOUT + f0) = o2;
}

extern "C" void kernel_launch(void* const* d_in, const int* in_sizes, int n_in,
                              void* d_out, int out_size) {
    const float* x     = (const float*)d_in[0];
    const int*   adj   = (const int*)  d_in[1];
    const float* W     = (const float*)d_in[2];
    const float* a     = (const float*)d_in[3];
    const float* gamma = (const float*)d_in[4];
    const float* beta  = (const float*)d_in[5];
    float* out = (float*)d_out;

    k1_fused<<<K1BLK + PACKBLK, 128>>>(x, W, a, adj);
    k2_attn<<<dim3(Nn / 64, Bb, NSTRIP), 128>>>();
    k3_fin<<<ROWS / 8, 256>>>(gamma, beta, out);
}

// round 9
// speedup vs baseline: 1.1128x; 1.1128x over previous
#include <cuda_runtime.h>
#include <cuda_fp16.h>

#define Bb   8
#define Nn   2048
#define FIN  128
#define FOUT 64
#define NSTRIP 2
#define JS   (Nn / NSTRIP)          // 1024 j per strip
#define ROWS (Bb * Nn)              // 16384
#define K1BLK 512                   // k1 blocks inside fused kernel
#define PACKBLK (ROWS / 4)          // 4096 pack blocks (4 warps x 1 row)

typedef unsigned int u32;

// ---------------- device scratch (no allocations allowed) ----------------
__device__ float g_E1[ROWS], g_E2[ROWS], g_F1[ROWS], g_F2[ROWS];
__device__ __half g_hHi[ROWS * FOUT];
__device__ u32   g_mask[ROWS * 64];              // 4.2 MB adjacency bitmask
__device__ float g_part[NSTRIP * ROWS * FOUT];   // 8.4 MB partial numerators
__device__ float g_den [NSTRIP * ROWS];          // partial denominators

// ---------------- MMA helpers (sm_80 baseline PTX) ----------------
__device__ __forceinline__ void ldsm4(u32& r0, u32& r1, u32& r2, u32& r3, u32 a) {
    asm volatile("ldmatrix.sync.aligned.m8n8.x4.shared.b16 {%0,%1,%2,%3}, [%4];"
                 : "=r"(r0), "=r"(r1), "=r"(r2), "=r"(r3) : "r"(a));
}
__device__ __forceinline__ void ldsm4t(u32& r0, u32& r1, u32& r2, u32& r3, u32 a) {
    asm volatile("ldmatrix.sync.aligned.m8n8.x4.trans.shared.b16 {%0,%1,%2,%3}, [%4];"
                 : "=r"(r0), "=r"(r1), "=r"(r2), "=r"(r3) : "r"(a));
}
__device__ __forceinline__ void ldsm2t(u32& r0, u32& r1, u32 a) {
    asm volatile("ldmatrix.sync.aligned.m8n8.x2.trans.shared.b16 {%0,%1}, [%2];"
                 : "=r"(r0), "=r"(r1) : "r"(a));
}
__device__ __forceinline__ void hmma(float* c, const u32* a, u32 b0, u32 b1) {
    asm volatile("mma.sync.aligned.m16n8k16.row.col.f32.f16.f16.f32 "
                 "{%0,%1,%2,%3}, {%4,%5,%6,%7}, {%8,%9}, {%0,%1,%2,%3};"
                 : "+f"(c[0]), "+f"(c[1]), "+f"(c[2]), "+f"(c[3])
                 : "r"(a[0]), "r"(a[1]), "r"(a[2]), "r"(a[3]), "r"(b0), "r"(b1));
}
__device__ __forceinline__ u32 smem_u32(const void* p) {
    u32 a;
    asm("{ .reg .u64 t; cvta.to.shared.u64 t, %1; cvt.u32.u64 %0, t; }" : "=r"(a) : "l"(p));
    return a;
}

// ---------------- K1 fused: proj (blocks < K1BLK) + adj bit-pack ----------
// Pack layout (straightforward): word w of row = bits for j in [w*32, w*32+32),
// bit k = adj[row][w*32+k]. Ballot-free: adj values are 0/1, bit = value.
__global__ __launch_bounds__(128) void k1_fused(const float* __restrict__ x,
                                                const float* __restrict__ W,
                                                const float* __restrict__ a,
                                                const int* __restrict__ adj) {
    __shared__ float sX[32][132];
    __shared__ float sW[FIN][FOUT];
    __shared__ float sa[2 * FOUT];
    __shared__ float sp1[32][17], sp2[32][17];

    int t = threadIdx.x;
    if (blockIdx.x >= K1BLK) {
        // ---- adjacency bit-pack: warp per row, lane owns 32 consecutive j --
        int lane = t & 31;
        int row = (blockIdx.x - K1BLK) * 4 + (t >> 5);
        const int4* rowp = (const int4*)(adj + (size_t)row * Nn);
        u32* mrow = g_mask + (size_t)row * 64;
#pragma unroll
        for (int it = 0; it < 2; it++) {
            int4 v[8];
#pragma unroll
            for (int q = 0; q < 8; q++) v[q] = rowp[it * 256 + lane * 8 + q];
            u32 word = 0;
#pragma unroll
            for (int q = 0; q < 8; q++) {
                u32 nib = ((u32)v[q].x & 1u) | (((u32)v[q].y & 1u) << 1)
                        | (((u32)v[q].z & 1u) << 2) | (((u32)v[q].w & 1u) << 3);
                word |= nib << (q * 4);
            }
            mrow[it * 32 + lane] = word;
        }
        return;
    }

    // ---- projection: h = x@W (f16), per-node exps ----
    int r0 = blockIdx.x * 32;
#pragma unroll
    for (int q = 0; q < 16; q++)
        ((float4*)sW)[t + q * 128] = ((const float4*)W)[t + q * 128];
    sa[t] = a[t];
#pragma unroll
    for (int q = 0; q < 8; q++) {
        int idx = t + q * 128;
        int row = idx >> 5, c4 = idx & 31;
        *(float4*)&sX[row][c4 * 4] = ((const float4*)(x + (size_t)(r0 + row) * FIN))[c4];
    }
    __syncthreads();

    int rowt = t >> 4, colt = t & 15;
    float acc[4][4] = {};
#pragma unroll 4
    for (int k = 0; k < FIN; k++) {
        float4 wv = *(const float4*)&sW[k][colt * 4];
        float x0 = sX[rowt * 4 + 0][k], x1 = sX[rowt * 4 + 1][k];
        float x2 = sX[rowt * 4 + 2][k], x3 = sX[rowt * 4 + 3][k];
        acc[0][0] = fmaf(x0, wv.x, acc[0][0]); acc[0][1] = fmaf(x0, wv.y, acc[0][1]);
        acc[0][2] = fmaf(x0, wv.z, acc[0][2]); acc[0][3] = fmaf(x0, wv.w, acc[0][3]);
        acc[1][0] = fmaf(x1, wv.x, acc[1][0]); acc[1][1] = fmaf(x1, wv.y, acc[1][1]);
        acc[1][2] = fmaf(x1, wv.z, acc[1][2]); acc[1][3] = fmaf(x1, wv.w, acc[1][3]);
        acc[2][0] = fmaf(x2, wv.x, acc[2][0]); acc[2][1] = fmaf(x2, wv.y, acc[2][1]);
        acc[2][2] = fmaf(x2, wv.z, acc[2][2]); acc[2][3] = fmaf(x2, wv.w, acc[2][3]);
        acc[3][0] = fmaf(x3, wv.x, acc[3][0]); acc[3][1] = fmaf(x3, wv.y, acc[3][1]);
        acc[3][2] = fmaf(x3, wv.z, acc[3][2]); acc[3][3] = fmaf(x3, wv.w, acc[3][3]);
    }

    float a1v[4] = {sa[colt * 4], sa[colt * 4 + 1], sa[colt * 4 + 2], sa[colt * 4 + 3]};
    float a2v[4] = {sa[64 + colt * 4], sa[64 + colt * 4 + 1],
                    sa[64 + colt * 4 + 2], sa[64 + colt * 4 + 3]};
#pragma unroll
    for (int r = 0; r < 4; r++) {
        int row = rowt * 4 + r;
        float p1 = acc[r][0] * a1v[0] + acc[r][1] * a1v[1]
                 + acc[r][2] * a1v[2] + acc[r][3] * a1v[3];
        float p2 = acc[r][0] * a2v[0] + acc[r][1] * a2v[1]
                 + acc[r][2] * a2v[2] + acc[r][3] * a2v[3];
        sp1[row][colt] = p1;
        sp2[row][colt] = p2;
        __half2 h0 = __floats2half2_rn(acc[r][0], acc[r][1]);
        __half2 h1 = __floats2half2_rn(acc[r][2], acc[r][3]);
        size_t o = (size_t)(r0 + row) * FOUT + colt * 4;
        *(uint2*)&g_hHi[o] = make_uint2(*(u32*)&h0, *(u32*)&h1);
    }
    __syncthreads();
    if (t < 32) {
        float s1 = 0.f, s2 = 0.f;
#pragma unroll
        for (int q = 0; q < 16; q++) { s1 += sp1[t][q]; s2 += sp2[t][q]; }
        int gr = r0 + t;
        g_E1[gr] = __expf(s1);  g_E2[gr] = __expf(0.2f * s1);
        g_F1[gr] = __expf(s2);  g_F2[gr] = __expf(0.2f * s2);
    }
}

// ---------------- K2: masked-softmax attention numerator via HMMA ----------
// grid (32 i-tiles, 8 b, 2 strips), 128 threads. adj via bitmask: one u32 per
// row-chunk per thread (broadcast LDG.32). Denominator via ones-column (col 64).
#define PSTRB 144   // bytes per smem tile row (72 f16: 64 data + 8 pad/ones)
__global__ __launch_bounds__(128, 6) void k2_attn() {
    __shared__ __align__(16) __half sPh [64 * 72];
    __shared__ __align__(16) __half sHhi[64 * 72];
    __shared__ float2 sF[64];
    __shared__ float  sE1[64], sE2[64];

    const int t = threadIdx.x, lane = t & 31, w = t >> 5;
    const int b = blockIdx.y, i0 = blockIdx.x * 64, strip = blockIdx.z;
    const int jbase = strip * JS;

    if (t < 64) { sE1[t] = g_E1[b * Nn + i0 + t]; sE2[t] = g_E2[b * Nn + i0 + t]; }
    // ones-column init (cols 64-71 pad region; phase1 never touches it)
    if (t < 64)
        *(uint4*)((char*)sHhi + t * PSTRB + 128) = make_uint4(0x00003C00u, 0, 0, 0);

    const int rg = t >> 4, jsw = t & 15, js = jsw * 4;
    const int mcol = jsw >> 3, msh = (jsw & 7) * 4;
    const u32* mbase = g_mask + (size_t)(b * Nn + i0) * 64;

    float acc[8][4];
#pragma unroll
    for (int n = 0; n < 8; n++)
#pragma unroll
        for (int q = 0; q < 4; q++) acc[n][q] = 0.f;
    float accD[4] = {0.f, 0.f, 0.f, 0.f};

    const u32 pHB = smem_u32(sPh);
    const u32 hHiB = smem_u32(sHhi);
    const u32 aOff = (u32)(w * 16 + (lane & 15)) * PSTRB + (u32)((lane >> 4) & 1) * 16;
    const u32 hRow = (u32)((lane & 7) + ((lane >> 4) & 1) * 8);
    const u32 hCol = (u32)((lane >> 3) & 1) * 16;
    const u32 oAddr0 = (u32)(lane & 15) * PSTRB;

    for (int c = 0; c < JS / 64; c++) {
        const int j0 = jbase + c * 64;
        const int wbase = (j0 >> 5) + mcol;
        __syncthreads();                              // previous MMA done
        // ---- phase 1: load h tile + F + mask words ----
        if (t < 64) sF[t] = make_float2(g_F1[b * Nn + j0 + t], g_F2[b * Nn + j0 + t]);
        u32 mw[8];
#pragma unroll
        for (int p = 0; p < 8; p++)
            mw[p] = mbase[(size_t)(p * 8 + rg) * 64 + wbase];
#pragma unroll
        for (int q = 0; q < 4; q++) {
            int u = t + q * 128;
            int row = u >> 3, c16 = u & 7;
            uint4 v = *(const uint4*)(g_hHi + ((size_t)(b * Nn) + j0 + row) * FOUT + c16 * 8);
            *(uint4*)((char*)sHhi + row * PSTRB + c16 * 16) = v;
        }
        __syncthreads();
        // ---- phase 2: P-gen (single f16 round) ----
        float2 f0 = sF[js], f1 = sF[js + 1], f2 = sF[js + 2], f3 = sF[js + 3];
#pragma unroll
        for (int p = 0; p < 8; p++) {
            int il = p * 8 + rg;
            float e1 = sE1[il], e2 = sE2[il];
            u32 nib = mw[p] >> msh;
            float w0 = (nib & 1u)        ? fmaxf(e1 * f0.x, e2 * f0.y) : 0.f;
            float w1 = ((nib >> 1) & 1u) ? fmaxf(e1 * f1.x, e2 * f1.y) : 0.f;
            float w2 = ((nib >> 2) & 1u) ? fmaxf(e1 * f2.x, e2 * f2.y) : 0.f;
            float w3 = ((nib >> 3) & 1u) ? fmaxf(e1 * f3.x, e2 * f3.y) : 0.f;
            __half2 q0 = __floats2half2_rn(w0, w1);
            __half2 q1 = __floats2half2_rn(w2, w3);
            *(uint2*)((char*)sPh + il * PSTRB + js * 2) = make_uint2(*(u32*)&q0, *(u32*)&q1);
        }
        __syncthreads();
        // ---- phase 3: MMA (P*Hhi + P*ones) ----
#pragma unroll
        for (int ks = 0; ks < 4; ks++) {
            u32 af[4];
            ldsm4(af[0], af[1], af[2], af[3], pHB + aOff + ks * 32);
            u32 ho = (u32)(ks * 16 + hRow) * PSTRB + hCol;
#pragma unroll
            for (int np = 0; np < 4; np++) {
                u32 b0, b1, b2, b3;
                ldsm4t(b0, b1, b2, b3, hHiB + ho + np * 32);
                hmma(acc[np * 2],     af, b0, b2);
                hmma(acc[np * 2 + 1], af, b1, b3);
            }
            u32 d0, d1;
            ldsm2t(d0, d1, hHiB + (u32)(ks * 16) * PSTRB + oAddr0 + 128);
            hmma(accD, af, d0, d1);
        }
    }

    // ---- denominator (ones column): lanes with lane%4==0 hold col 64 ----
    if ((lane & 3) == 0) {
        size_t dbase = (size_t)strip * ROWS + b * Nn + i0 + w * 16 + (lane >> 2);
        g_den[dbase]     = accD[0];
        g_den[dbase + 8] = accD[2];
    }

    // ---- numerator partials: D fragments -> g_part ----
    float* base = g_part + (((size_t)strip * ROWS) + b * Nn + i0 + w * 16 + (lane >> 2))
                           * FOUT + (lane & 3) * 2;
#pragma unroll
    for (int nt = 0; nt < 8; nt++) {
        *(float2*)(base + nt * 8)            = make_float2(acc[nt][0], acc[nt][1]);
        *(float2*)(base + 8 * FOUT + nt * 8) = make_float2(acc[nt][2], acc[nt][3]);
    }
}

// ---------------- K3: combine strips, softmax-normalize, LN + ELU ----------
__global__ __launch_bounds__(256) void k3_fin(const float* __restrict__ gamma,
                                              const float* __restrict__ beta,
                                              float* __restrict__ out) {
    int warp = threadIdx.x >> 5, lane = threadIdx.x & 31;
    size_t row = (size_t)blockIdx.x * 8 + warp;
    int f0 = lane * 2;
    float2 v = make_float2(0.f, 0.f);
    float den = 0.f;
#pragma unroll
    for (int s = 0; s < NSTRIP; s++) {
        float2 pv = *(const float2*)(g_part + ((size_t)s * ROWS + row) * FOUT + f0);
        v.x += pv.x; v.y += pv.y;
        den += g_den[(size_t)s * ROWS + row];
    }
    float rinv = __fdividef(1.0f, den);
    v.x *= rinv; v.y *= rinv;
    float sum = v.x + v.y;
#pragma unroll
    for (int o = 16; o; o >>= 1) sum += __shfl_xor_sync(0xffffffffu, sum, o);
    float mu = sum * (1.0f / 64.0f);
    float dx = v.x - mu, dy = v.y - mu;
    float q = dx * dx + dy * dy;
#pragma unroll
    for (int o = 16; o; o >>= 1) q += __shfl_xor_sync(0xffffffffu, q, o);
    float rstd = rsqrtf(q * (1.0f / 64.0f) + 1e-5f);
    float y0 = dx * rstd * gamma[f0]     + beta[f0];
    float y1 = dy * rstd * gamma[f0 + 1] + beta[f0 + 1];
    float2 o2;
    o2.x = (y0 > 0.f) ? y0 : (__expf(y0) - 1.0f);
    o2.y = (y1 > 0.f) ? y1 : (__expf(y1) - 1.0f);
    *(float2*)(out + row * FOUT + f0) = o2;
}

extern "C" void kernel_launch(void* const* d_in, const int* in_sizes, int n_in,
                              void* d_out, int out_size) {
    const float* x     = (const float*)d_in[0];
    const int*   adj   = (const int*)  d_in[1];
    const float* W     = (const float*)d_in[2];
    const float* a     = (const float*)d_in[3];
    const float* gamma = (const float*)d_in[4];
    const float* beta  = (const float*)d_in[5];
    float* out = (float*)d_out;

    k1_fused<<<K1BLK + PACKBLK, 128>>>(x, W, a, adj);
    k2_attn<<<dim3(Nn / 64, Bb, NSTRIP), 128>>>();
    k3_fin<<<ROWS / 8, 256>>>(gamma, beta, out);
}